// round 17
// baseline (speedup 1.0000x reference)
#include <cuda_runtime.h>
#include <cuda_bf16.h>
#include <cstdint>
#include <cstddef>

// ---------------------------------------------------------------------------
// RGAT layer. GEMM: mma.sync m16n8k16 bf16 split-precision (3 products,
// ldmatrix.x4, 4m x 2n warp tiles) — R14 form, measured win.
// Edge phase: R4 form + 2-edge-per-warp ILP batching.
// init split into slot_init + zero_out so ncu's 4th-launch capture lands on
// attn_kernel (attribution for the next round's decision).
//
// Shapes: x[50000,128] f32, W[8,128,128] f32,
//         edge_index[2,600000] i32, edge_type[600000] i32, out[50000,128] f32
// ---------------------------------------------------------------------------

#define N_NODES 50000
#define N_EDGES 600000
#define DIM     128
#define N_REL   8

__device__ float    g_h[(size_t)N_REL * N_NODES * DIM];   // 204.8 MB
__device__ float    g_attn[N_EDGES];
__device__ unsigned g_relmax[N_REL];
__device__ float    g_relsum[N_REL];

// ---- helpers --------------------------------------------------------------

__device__ __forceinline__ unsigned f2ord(float f) {
    unsigned b = __float_as_uint(f);
    return (b & 0x80000000u) ? ~b : (b | 0x80000000u);
}
__device__ __forceinline__ float ord2f(unsigned u) {
    return (u & 0x80000000u) ? __uint_as_float(u & 0x7fffffffu)
                             : __uint_as_float(~u);
}
__device__ __forceinline__ void mma_bf16(float* c,
                                         uint32_t a0, uint32_t a1,
                                         uint32_t a2, uint32_t a3,
                                         uint32_t b0, uint32_t b1) {
    asm volatile(
        "mma.sync.aligned.m16n8k16.row.col.f32.bf16.bf16.f32 "
        "{%0,%1,%2,%3}, {%4,%5,%6,%7}, {%8,%9}, {%0,%1,%2,%3};"
        : "+f"(c[0]), "+f"(c[1]), "+f"(c[2]), "+f"(c[3])
        : "r"(a0), "r"(a1), "r"(a2), "r"(a3), "r"(b0), "r"(b1));
}
__device__ __forceinline__ void ldsm4(uint32_t& r0, uint32_t& r1,
                                      uint32_t& r2, uint32_t& r3,
                                      uint32_t addr) {
    asm volatile(
        "ldmatrix.sync.aligned.m8n8.x4.shared.b16 {%0,%1,%2,%3}, [%4];"
        : "=r"(r0), "=r"(r1), "=r"(r2), "=r"(r3) : "r"(addr));
}

// ---- kernel 1: init reduction slots (tiny; shifts ncu capture slot) ---------

__global__ void slot_init_kernel() {
    if (threadIdx.x < N_REL) {
        g_relmax[threadIdx.x] = 0u;   // ord(-inf)
        g_relsum[threadIdx.x] = 0.f;
    }
}

// ---- kernel 2: zero output --------------------------------------------------

__global__ void zero_out_kernel(float4* __restrict__ out) {
    int n = N_NODES * DIM / 4;
    float4 z = make_float4(0.f, 0.f, 0.f, 0.f);
    for (int i = blockIdx.x * blockDim.x + threadIdx.x; i < n;
         i += gridDim.x * blockDim.x)
        out[i] = z;
}

// ---- gemm: h[r] = x @ W[r], bf16 hi/lo, mma.sync + ldmatrix (R14) -----------

#define GBM 128
#define GS  136
#define SM_A_HI 0
#define SM_A_LO (128 * GS)
#define SM_B_HI (2 * 128 * GS)
#define SM_B_LO (3 * 128 * GS)
#define GEMM_SMEM_BYTES (4 * 128 * GS * 2)

__global__ void __launch_bounds__(256, 1)
gemm_kernel(const float* __restrict__ x, const float* __restrict__ W) {
    extern __shared__ __nv_bfloat16 sm[];
    const int r    = blockIdx.y;
    const int row0 = blockIdx.x * GBM;
    const int tid  = threadIdx.x;

    {
        const float4* xv = (const float4*)x;
        for (int i = tid; i < GBM * (DIM / 4); i += 256) {
            int m  = i >> 5;
            int c4 = i & 31;
            int gr = row0 + m;
            float4 v = (gr < N_NODES) ? xv[(size_t)gr * 32 + c4]
                                      : make_float4(0.f, 0.f, 0.f, 0.f);
            float vs[4] = {v.x, v.y, v.z, v.w};
            #pragma unroll
            for (int j = 0; j < 4; j++) {
                __nv_bfloat16 hi = __float2bfloat16(vs[j]);
                __nv_bfloat16 lo =
                    __float2bfloat16(vs[j] - __bfloat162float(hi));
                int o = m * GS + c4 * 4 + j;
                sm[SM_A_HI + o] = hi;
                sm[SM_A_LO + o] = lo;
            }
        }
    }
    {
        const float* Wr = W + (size_t)r * DIM * DIM;
        for (int i = tid; i < DIM * DIM; i += 256) {
            int n = i & 127;
            int k = i >> 7;
            float w = Wr[k * DIM + n];
            __nv_bfloat16 hi = __float2bfloat16(w);
            __nv_bfloat16 lo = __float2bfloat16(w - __bfloat162float(hi));
            int o = n * GS + k;
            sm[SM_B_HI + o] = hi;
            sm[SM_B_LO + o] = lo;
        }
    }
    __syncthreads();

    const int w    = tid >> 5;
    const int lane = tid & 31;
    const int qr   = lane >> 2;
    const int qc   = (lane & 3) * 2;
    const int mb   = (w >> 1) * 32;
    const int nb   = (w & 1) * 64;

    const int q  = lane >> 3;
    const int i8 = lane & 7;
    const uint32_t smb = (uint32_t)__cvta_generic_to_shared(sm);
    const uint32_t aH0 = smb + 2u * (SM_A_HI + (mb + (q & 1) * 8 + i8) * GS
                                     + (q >> 1) * 8);
    const uint32_t aH1 = aH0 + 2u * 16 * GS;
    const uint32_t aL0 = aH0 + 2u * (SM_A_LO - SM_A_HI);
    const uint32_t aL1 = aL0 + 2u * 16 * GS;
    const uint32_t bA  = smb + 2u * (SM_B_HI + (q >> 1) * (SM_B_LO - SM_B_HI)
                                     + (nb + i8) * GS + (q & 1) * 8);

    float acc[2][8][4];
    #pragma unroll
    for (int mt = 0; mt < 2; mt++)
        #pragma unroll
        for (int nt = 0; nt < 8; nt++)
            #pragma unroll
            for (int j = 0; j < 4; j++) acc[mt][nt][j] = 0.f;

    #pragma unroll
    for (int k0 = 0; k0 < DIM; k0 += 16) {
        uint32_t ah[2][4], al[2][4];
        ldsm4(ah[0][0], ah[0][1], ah[0][2], ah[0][3], aH0 + 2u * k0);
        ldsm4(ah[1][0], ah[1][1], ah[1][2], ah[1][3], aH1 + 2u * k0);
        ldsm4(al[0][0], al[0][1], al[0][2], al[0][3], aL0 + 2u * k0);
        ldsm4(al[1][0], al[1][1], al[1][2], al[1][3], aL1 + 2u * k0);

        #pragma unroll
        for (int nt = 0; nt < 8; nt++) {
            uint32_t bh0, bh1, bl0, bl1;
            ldsm4(bh0, bh1, bl0, bl1, bA + 2u * (nt * 8 * GS + k0));
            #pragma unroll
            for (int mt = 0; mt < 2; mt++) {
                mma_bf16(acc[mt][nt], ah[mt][0], ah[mt][1], ah[mt][2],
                         ah[mt][3], bh0, bh1);
                mma_bf16(acc[mt][nt], al[mt][0], al[mt][1], al[mt][2],
                         al[mt][3], bh0, bh1);
                mma_bf16(acc[mt][nt], ah[mt][0], ah[mt][1], ah[mt][2],
                         ah[mt][3], bl0, bl1);
            }
        }
    }

    float* hb = g_h + (size_t)r * N_NODES * DIM;
    #pragma unroll
    for (int mt = 0; mt < 2; mt++) {
        const int gr0 = row0 + mb + mt * 16 + qr;
        const int gr1 = gr0 + 8;
        #pragma unroll
        for (int nt = 0; nt < 8; nt++) {
            const int n0 = nb + nt * 8 + qc;
            if (gr0 < N_NODES)
                *(float2*)(hb + (size_t)gr0 * DIM + n0) =
                    make_float2(acc[mt][nt][0], acc[mt][nt][1]);
            if (gr1 < N_NODES)
                *(float2*)(hb + (size_t)gr1 * DIM + n0) =
                    make_float2(acc[mt][nt][2], acc[mt][nt][3]);
        }
    }
}

// ---- attn: 2 edges per warp iteration (ILP), leaky_relu + relation max ------

__global__ void attn_kernel(const int* __restrict__ ei,
                            const int* __restrict__ et) {
    __shared__ unsigned smax[N_REL];
    const int tid = threadIdx.x;
    if (tid < N_REL) smax[tid] = 0u;
    __syncthreads();

    const int lane = tid & 31;
    const int gw   = (blockIdx.x * blockDim.x + tid) >> 5;
    const int nw   = (gridDim.x * blockDim.x) >> 5;

    for (int e = 2 * gw; e < N_EDGES; e += 2 * nw) {
        // N_EDGES even and e even -> e+1 always valid
        int t0 = et[e],     s0 = ei[e],     d0 = ei[N_EDGES + e];
        int t1 = et[e + 1], s1 = ei[e + 1], d1 = ei[N_EDGES + e + 1];
        const float4* p0s = (const float4*)(g_h + ((size_t)t0 * N_NODES + s0) * DIM);
        const float4* p0d = (const float4*)(g_h + ((size_t)t0 * N_NODES + d0) * DIM);
        const float4* p1s = (const float4*)(g_h + ((size_t)t1 * N_NODES + s1) * DIM);
        const float4* p1d = (const float4*)(g_h + ((size_t)t1 * N_NODES + d1) * DIM);
        float4 a0 = p0s[lane], b0 = p0d[lane];
        float4 a1 = p1s[lane], b1 = p1d[lane];
        float v0 = a0.x * b0.x + a0.y * b0.y + a0.z * b0.z + a0.w * b0.w;
        float v1 = a1.x * b1.x + a1.y * b1.y + a1.z * b1.z + a1.w * b1.w;
        // interleaved butterfly chains (independent -> overlapped latency)
        v0 += __shfl_xor_sync(0xffffffffu, v0, 16);
        v1 += __shfl_xor_sync(0xffffffffu, v1, 16);
        v0 += __shfl_xor_sync(0xffffffffu, v0, 8);
        v1 += __shfl_xor_sync(0xffffffffu, v1, 8);
        v0 += __shfl_xor_sync(0xffffffffu, v0, 4);
        v1 += __shfl_xor_sync(0xffffffffu, v1, 4);
        v0 += __shfl_xor_sync(0xffffffffu, v0, 2);
        v1 += __shfl_xor_sync(0xffffffffu, v1, 2);
        v0 += __shfl_xor_sync(0xffffffffu, v0, 1);
        v1 += __shfl_xor_sync(0xffffffffu, v1, 1);
        if (lane == 0) {
            v0 = (v0 > 0.f) ? v0 : 0.2f * v0;
            v1 = (v1 > 0.f) ? v1 : 0.2f * v1;
            g_attn[e]     = v0;
            g_attn[e + 1] = v1;
            atomicMax(&smax[t0], f2ord(v0));
            atomicMax(&smax[t1], f2ord(v1));
        }
    }
    __syncthreads();
    if (tid < N_REL) atomicMax(&g_relmax[tid], smax[tid]);
}

// ---- softmax: exp(attn - max[rel]) in place + per-relation sum --------------

__global__ void softmax_kernel(const int* __restrict__ et) {
    __shared__ float ssum[N_REL];
    __shared__ float smx[N_REL];
    const int tid = threadIdx.x;
    if (tid < N_REL) {
        ssum[tid] = 0.f;
        smx[tid]  = ord2f(g_relmax[tid]);
    }
    __syncthreads();

    const int stride = gridDim.x * blockDim.x;
    for (int e = blockIdx.x * blockDim.x + tid; e < N_EDGES; e += stride) {
        int t = et[e];
        float ex = expf(g_attn[e] - smx[t]);
        g_attn[e] = ex;
        atomicAdd(&ssum[t], ex);
    }
    __syncthreads();
    if (tid < N_REL) atomicAdd(&g_relsum[tid], ssum[tid]);
}

// ---- scatter: 2 edges per warp iteration, vector RED ------------------------

__global__ void scatter_kernel(const int* __restrict__ ei,
                               const int* __restrict__ et,
                               float* __restrict__ out) {
    const int tid  = threadIdx.x;
    const int lane = tid & 31;
    const int gw   = (blockIdx.x * blockDim.x + tid) >> 5;
    const int nw   = (gridDim.x * blockDim.x) >> 5;

    for (int e = 2 * gw; e < N_EDGES; e += 2 * nw) {
        int t0 = et[e],     s0 = ei[e],     d0 = ei[N_EDGES + e];
        int t1 = et[e + 1], s1 = ei[e + 1], d1 = ei[N_EDGES + e + 1];
        float a0 = g_attn[e]     / g_relsum[t0];
        float a1 = g_attn[e + 1] / g_relsum[t1];
        const float4* p0 = (const float4*)(g_h + ((size_t)t0 * N_NODES + s0) * DIM);
        const float4* p1 = (const float4*)(g_h + ((size_t)t1 * N_NODES + s1) * DIM);
        float4 v0 = p0[lane];
        float4 v1 = p1[lane];
        float* o0 = out + (size_t)d0 * DIM + lane * 4;
        float* o1 = out + (size_t)d1 * DIM + lane * 4;
        asm volatile("red.global.add.v4.f32 [%0], {%1, %2, %3, %4};"
                     :: "l"(o0), "f"(v0.x * a0), "f"(v0.y * a0),
                        "f"(v0.z * a0), "f"(v0.w * a0)
                     : "memory");
        asm volatile("red.global.add.v4.f32 [%0], {%1, %2, %3, %4};"
                     :: "l"(o1), "f"(v1.x * a1), "f"(v1.y * a1),
                        "f"(v1.z * a1), "f"(v1.w * a1)
                     : "memory");
    }
}

// ---- launch ----------------------------------------------------------------

extern "C" void kernel_launch(void* const* d_in, const int* in_sizes, int n_in,
                              void* d_out, int out_size) {
    const float* x  = (const float*)d_in[0];
    const float* W  = (const float*)d_in[1];
    const int*   ei = (const int*)d_in[2];
    const int*   et = (const int*)d_in[3];
    float* out = (float*)d_out;

    slot_init_kernel<<<1, 32>>>();                    // launch 1
    zero_out_kernel<<<1024, 256>>>((float4*)out);     // launch 2

    cudaFuncSetAttribute(gemm_kernel,
                         cudaFuncAttributeMaxDynamicSharedMemorySize,
                         GEMM_SMEM_BYTES);
    dim3 gg((N_NODES + GBM - 1) / GBM, N_REL);
    gemm_kernel<<<gg, 256, GEMM_SMEM_BYTES>>>(x, W);  // launch 3

    attn_kernel<<<1184, 256>>>(ei, et);               // launch 4 <- ncu slot
    softmax_kernel<<<592, 256>>>(et);                 // launch 5
    scatter_kernel<<<1184, 256>>>(ei, et, out);       // launch 6
}